// round 1
// baseline (speedup 1.0000x reference)
#include <cuda_runtime.h>

// SVD_9990093931239 — batched Kabsch alignment, algebraically collapsed.
//
// Reference math:
//   tt = src + pose  ->  tt_c == src_c  ->  H = src_c @ src_c^T  (symmetric PSD)
//   SVD of symmetric PSD: U == V  ->  R0 = V U^T == I, det(R0) = +1 (no reflection)
//   t = -R src_mean + tt_mean = pose
// So the exact output is R = I (per batch), t = pose. No input reads of
// source/template needed; noise vs reference is the reference's own f32 SVD
// backward error (~1e-6), well under the 1e-3 gate.

__global__ void svd_identity_pose_kernel(const float* __restrict__ pose,
                                         float* __restrict__ out,
                                         int r_elems,   // B*9
                                         int total)     // out_size
{
    int idx = blockIdx.x * blockDim.x + threadIdx.x;
    if (idx >= total) return;

    float v;
    if (idx < r_elems) {
        int r = idx % 9;                       // position within 3x3
        v = (r == 0 || r == 4 || r == 8) ? 1.0f : 0.0f;
    } else {
        v = pose[idx - r_elems];               // t[b,i] = pose[b,i,0]
    }
    out[idx] = v;
}

extern "C" void kernel_launch(void* const* d_in, const int* in_sizes, int n_in,
                              void* d_out, int out_size)
{
    // inputs: [0]=source [B,N,3], [1]=template [B,N,3], [2]=pose [B,3,1]
    const float* pose = (const float*)d_in[2];
    float* out = (float*)d_out;

    const int B = in_sizes[2] / 3;   // pose has B*3 elements
    const int r_elems = B * 9;

    const int threads = 256;
    const int blocks = (out_size + threads - 1) / threads;
    svd_identity_pose_kernel<<<blocks, threads>>>(pose, out, r_elems, out_size);
}